// round 1
// baseline (speedup 1.0000x reference)
#include <cuda_runtime.h>
#include <math.h>

#define BB 2
#define LL 512
#define HH 768
#define EE 512
#define RR 32768
#define HD2 384           // H/2
#define BE (BB*EE)        // 1024 distinct entities
#define NREL (BB*RR)      // 65536 relations
#define RELBLOCKS (NREL/8) // 8192 blocks * 8 warps

// ---------------- scratch (static device globals; no allocation) ------------
__device__ __align__(16) float g_repr [BE * 2 * HH];   // [1024,1536]
__device__ __align__(16) float g_hidh [BE * HH];       // head MLP hidden
__device__ __align__(16) float g_hidt [BE * HH];       // tail MLP hidden
__device__ __align__(16) float g_heads[BE * HD2];      // [1024,384]
__device__ __align__(16) float g_tails[BE * HD2];
__device__ __align__(16) float g_u    [BE * 2 * HD2];  // [1024][o=2][384]
__device__ __align__(16) float g_lin4 [BE * 4];        // lh0,lh1,lt0,lt1
__device__                float g_partial[RELBLOCKS];

// ---------------- kernel 1: build entity representations --------------------
__global__ void build_repr(const float* __restrict__ hidden,
                           const int*   __restrict__ ent_start,
                           const int*   __restrict__ ent_label,
                           const float* __restrict__ entity_emb) {
    int eg  = blockIdx.x;           // 0..1023 (flattened [B,E])
    int b   = eg / EE;
    int idx = ent_start[eg];
    int lab = ent_label[eg];
    const float4* tok = (const float4*)(hidden + (size_t)(b * LL + idx) * HH);
    const float4* emb = (const float4*)(entity_emb + (size_t)lab * HH);
    float4* dst = (float4*)(g_repr + (size_t)eg * 2 * HH);
    for (int i = threadIdx.x; i < HH / 4; i += blockDim.x) {
        dst[i]          = tok[i];
        dst[i + HH / 4] = emb[i];
    }
}

// ---------------- kernel 2: tiled fp32 GEMM (64x64x16), opt bias/ReLU -------
// C[M,N] = A[M,K] * B ; B is [K,N] row-major, or [N,K] row-major if TRANSB.
template<bool TRANSB, bool RELU>
__global__ void gemm64(const float* __restrict__ A, const float* __restrict__ B,
                       const float* __restrict__ bias, float* __restrict__ C,
                       int M, int N, int K) {
    const int BM = 64, BN = 64, BK = 16;
    __shared__ float As[BK][BM];
    __shared__ float Bs[BK][BN];
    int tid = threadIdx.x;
    int tx = tid & 15, ty = tid >> 4;
    int m0 = blockIdx.y * BM, n0 = blockIdx.x * BN;
    float acc[4][4] = {};

    for (int k0 = 0; k0 < K; k0 += BK) {
        { // A tile: 64 rows x 16 k, one float4 per thread, store transposed
            int row = tid >> 2;
            int kc  = (tid & 3) * 4;
            float4 a = *(const float4*)(A + (size_t)(m0 + row) * K + k0 + kc);
            As[kc + 0][row] = a.x; As[kc + 1][row] = a.y;
            As[kc + 2][row] = a.z; As[kc + 3][row] = a.w;
        }
        if (!TRANSB) { // B tile: 16 k-rows x 64 n
            int kr = tid >> 4;
            int nc = (tid & 15) * 4;
            float4 bv = *(const float4*)(B + (size_t)(k0 + kr) * N + n0 + nc);
            *(float4*)&Bs[kr][nc] = bv;
        } else {       // B is [N,K]: 64 n-rows x 16 k, store transposed
            int nrow = tid >> 2;
            int kc   = (tid & 3) * 4;
            float4 bv = *(const float4*)(B + (size_t)(n0 + nrow) * K + k0 + kc);
            Bs[kc + 0][nrow] = bv.x; Bs[kc + 1][nrow] = bv.y;
            Bs[kc + 2][nrow] = bv.z; Bs[kc + 3][nrow] = bv.w;
        }
        __syncthreads();
#pragma unroll
        for (int kk = 0; kk < BK; kk++) {
            float4 a  = *(float4*)&As[kk][ty * 4];
            float4 bv = *(float4*)&Bs[kk][tx * 4];
            float av[4] = {a.x, a.y, a.z, a.w};
            float bw[4] = {bv.x, bv.y, bv.z, bv.w};
#pragma unroll
            for (int i = 0; i < 4; i++)
#pragma unroll
                for (int j = 0; j < 4; j++) acc[i][j] += av[i] * bw[j];
        }
        __syncthreads();
    }
#pragma unroll
    for (int i = 0; i < 4; i++) {
        int row = m0 + ty * 4 + i;
        float4 v;
        float* vp = (float*)&v;
#pragma unroll
        for (int j = 0; j < 4; j++) {
            float t = acc[i][j];
            if (bias) t += bias[n0 + tx * 4 + j];
            if (RELU) t = fmaxf(t, 0.0f);
            vp[j] = t;
        }
        *(float4*)(C + (size_t)row * N + n0 + tx * 4) = v;
    }
}

// ---------------- kernel 3: per-entity linear-term dots ---------------------
__global__ void lin_kernel(const float* __restrict__ lin_W) {
    int gw   = (blockIdx.x * blockDim.x + threadIdx.x) >> 5;
    int lane = threadIdx.x & 31;
    if (gw >= BE) return;
    const float* h = g_heads + (size_t)gw * HD2;
    const float* t = g_tails + (size_t)gw * HD2;
    float a0 = 0, a1 = 0, a2 = 0, a3 = 0;
    for (int d = lane; d < HD2; d += 32) {
        float hw = h[d], tw = t[d];
        a0 += hw * lin_W[d * 2 + 0];
        a1 += hw * lin_W[d * 2 + 1];
        a2 += tw * lin_W[(HD2 + d) * 2 + 0];
        a3 += tw * lin_W[(HD2 + d) * 2 + 1];
    }
#pragma unroll
    for (int o = 16; o > 0; o >>= 1) {
        a0 += __shfl_down_sync(~0u, a0, o);
        a1 += __shfl_down_sync(~0u, a1, o);
        a2 += __shfl_down_sync(~0u, a2, o);
        a3 += __shfl_down_sync(~0u, a3, o);
    }
    if (lane == 0) {
        float* p = g_lin4 + (size_t)gw * 4;
        p[0] = a0; p[1] = a1; p[2] = a2; p[3] = a3;
    }
}

// ---------------- kernel 4: per-relation logits + CE partial sums -----------
__global__ void rel_kernel(const int* __restrict__ rel_head,
                           const int* __restrict__ rel_tail,
                           const int* __restrict__ rel_label,
                           const float* __restrict__ lin_b,
                           float* __restrict__ logits_out) {
    __shared__ float wsum[8];
    int warp = threadIdx.x >> 5, lane = threadIdx.x & 31;
    int gr = blockIdx.x * 8 + warp;          // 0..65535
    int b  = gr >> 15;                       // / RR
    int he = rel_head[gr], te = rel_tail[gr];
    const float4* hv = (const float4*)(g_heads + (size_t)(b * EE + he) * HD2);
    const float4* uv = (const float4*)(g_u + (size_t)(b * EE + te) * 2 * HD2);
    float a0 = 0.0f, a1 = 0.0f;
#pragma unroll
    for (int i = 0; i < 3; i++) {            // 96 float4 per 384-vec
        int idx = lane + i * 32;
        float4 h  = hv[idx];
        float4 u0 = uv[idx];
        float4 u1 = uv[idx + 96];
        a0 += h.x * u0.x + h.y * u0.y + h.z * u0.z + h.w * u0.w;
        a1 += h.x * u1.x + h.y * u1.y + h.z * u1.z + h.w * u1.w;
    }
#pragma unroll
    for (int o = 16; o > 0; o >>= 1) {
        a0 += __shfl_down_sync(~0u, a0, o);
        a1 += __shfl_down_sync(~0u, a1, o);
    }
    if (lane == 0) {
        const float* lh = g_lin4 + (size_t)(b * EE + he) * 4;
        const float* lt = g_lin4 + (size_t)(b * EE + te) * 4;
        float s0 = a0 + lh[0] + lt[2] + lin_b[0];
        float s1 = a1 + lh[1] + lt[3] + lin_b[1];
        logits_out[(size_t)gr * 2 + 0] = s0;
        logits_out[(size_t)gr * 2 + 1] = s1;
        int lab = rel_label[gr];
        float m   = fmaxf(s0, s1);
        float lse = m + logf(expf(s0 - m) + expf(s1 - m));
        wsum[warp] = lse - (lab ? s1 : s0);
    }
    __syncthreads();
    if (threadIdx.x == 0) {
        float s = 0.0f;
#pragma unroll
        for (int w = 0; w < 8; w++) s += wsum[w];
        g_partial[blockIdx.x] = s;
    }
}

// ---------------- kernel 5: deterministic final loss reduction --------------
__global__ void finalize(float* __restrict__ out, int write_loss) {
    __shared__ float s[256];
    float acc = 0.0f;
    for (int i = threadIdx.x; i < RELBLOCKS; i += 256) acc += g_partial[i];
    s[threadIdx.x] = acc;
    __syncthreads();
    for (int st = 128; st > 0; st >>= 1) {
        if (threadIdx.x < st) s[threadIdx.x] += s[threadIdx.x + st];
        __syncthreads();
    }
    if (threadIdx.x == 0 && write_loss) out[0] = s[0] / (float)RR;
}

// ---------------- launcher ---------------------------------------------------
extern "C" void kernel_launch(void* const* d_in, const int* in_sizes, int n_in,
                              void* d_out, int out_size) {
    const float* hidden     = (const float*)d_in[0];
    const int*   ent_start  = (const int*)  d_in[1];
    const int*   ent_label  = (const int*)  d_in[2];
    const int*   rel_head   = (const int*)  d_in[3];
    const int*   rel_tail   = (const int*)  d_in[4];
    const int*   rel_label  = (const int*)  d_in[5];
    const float* entity_emb = (const float*)d_in[6];
    const float* head_W1 = (const float*)d_in[7];
    const float* head_b1 = (const float*)d_in[8];
    const float* head_W2 = (const float*)d_in[9];
    const float* head_b2 = (const float*)d_in[10];
    const float* tail_W1 = (const float*)d_in[11];
    const float* tail_b1 = (const float*)d_in[12];
    const float* tail_W2 = (const float*)d_in[13];
    const float* tail_b2 = (const float*)d_in[14];
    const float* bil_W   = (const float*)d_in[15];
    const float* lin_W   = (const float*)d_in[16];
    const float* lin_b   = (const float*)d_in[17];
    float* out = (float*)d_out;

    // Cache symbol addresses on the first (non-captured, correctness) call.
    static float* p_repr = nullptr;
    static float *p_hidh, *p_hidt, *p_heads, *p_tails, *p_u;
    if (!p_repr) {
        cudaGetSymbolAddress((void**)&p_repr,  g_repr);
        cudaGetSymbolAddress((void**)&p_hidh,  g_hidh);
        cudaGetSymbolAddress((void**)&p_hidt,  g_hidt);
        cudaGetSymbolAddress((void**)&p_heads, g_heads);
        cudaGetSymbolAddress((void**)&p_tails, g_tails);
        cudaGetSymbolAddress((void**)&p_u,     g_u);
    }

    int loff = out_size - 2 * NREL;          // 1 if loss slot precedes logits
    if (loff < 0) loff = 0;
    float* logits_out = out + loff;

    build_repr<<<BE, 256>>>(hidden, ent_start, ent_label, entity_emb);

    // MLP layer 1: [1024,1536] x [1536,768]  (+bias, ReLU)
    gemm64<false, true><<<dim3(HH / 64, BE / 64), 256>>>(
        p_repr, head_W1, head_b1, p_hidh, BE, HH, 2 * HH);
    gemm64<false, true><<<dim3(HH / 64, BE / 64), 256>>>(
        p_repr, tail_W1, tail_b1, p_hidt, BE, HH, 2 * HH);

    // MLP layer 2: [1024,768] x [768,384]  (+bias, ReLU)
    gemm64<false, true><<<dim3(HD2 / 64, BE / 64), 256>>>(
        p_hidh, head_W2, head_b2, p_heads, BE, HD2, HH);
    gemm64<false, true><<<dim3(HD2 / 64, BE / 64), 256>>>(
        p_hidt, tail_W2, tail_b2, p_tails, BE, HD2, HH);

    // u[e, o*384+d] = sum_k tails[e,k] * bil_W[o,d,k]  (B transposed view)
    gemm64<true, false><<<dim3(2 * HD2 / 64, BE / 64), 256>>>(
        p_tails, bil_W, nullptr, p_u, BE, 2 * HD2, HD2);

    lin_kernel<<<BE * 32 / 256, 256>>>(lin_W);

    rel_kernel<<<RELBLOCKS, 256>>>(rel_head, rel_tail, rel_label, lin_b,
                                   logits_out);
    finalize<<<1, 256>>>(out, loff > 0 ? 1 : 0);
}

// round 2
// speedup vs baseline: 2.3121x; 2.3121x over previous
#include <cuda_runtime.h>
#include <cuda_bf16.h>
#include <math.h>
#include <stdint.h>

#define BB 2
#define LL 512
#define HH 768
#define EE 512
#define RR 32768
#define HD2 384
#define BE (BB*EE)
#define NREL (BB*RR)
#define RELBLOCKS (NREL/8)

typedef __nv_bfloat16 bf16;

// ---------------- static scratch ---------------------------------------------
__device__ __align__(16) bf16 g_repr_hi[BE*2*HH], g_repr_lo[BE*2*HH];   // [1024][1536]
__device__ __align__(16) bf16 g_w1h_hi[HH*2*HH],  g_w1h_lo[HH*2*HH];    // [768][1536]
__device__ __align__(16) bf16 g_w1t_hi[HH*2*HH],  g_w1t_lo[HH*2*HH];
__device__ __align__(16) bf16 g_w2h_hi[HD2*HH],   g_w2h_lo[HD2*HH];     // [384][768]
__device__ __align__(16) bf16 g_w2t_hi[HD2*HH],   g_w2t_lo[HD2*HH];
__device__ __align__(16) bf16 g_bw_hi[2*HD2*HD2], g_bw_lo[2*HD2*HD2];   // [768][384]
__device__ __align__(16) bf16 g_hidh_hi[BE*HH],   g_hidh_lo[BE*HH];     // [1024][768]
__device__ __align__(16) bf16 g_hidt_hi[BE*HH],   g_hidt_lo[BE*HH];
__device__ __align__(16) bf16 g_tls_hi[BE*HD2],   g_tls_lo[BE*HD2];     // [1024][384]
__device__ __align__(16) float g_heads[BE*HD2];
__device__ __align__(16) float g_tails[BE*HD2];
__device__ __align__(16) float g_u[BE*2*HD2];
__device__ __align__(16) float g_lin4[BE*4];
__device__                float g_partial[RELBLOCKS];

__device__ __forceinline__ void split2(float v, bf16& h, bf16& l) {
    h = __float2bfloat16(v);
    l = __float2bfloat16(v - __bfloat162float(h));
}

// ---------------- kernel: gather + split entity representations --------------
__global__ void build_repr_split(const float* __restrict__ hidden,
                                 const int*   __restrict__ ent_start,
                                 const int*   __restrict__ ent_label,
                                 const float* __restrict__ entity_emb) {
    int eg = blockIdx.x;
    int b  = eg / EE;
    int idx = __ldg(&ent_start[eg]);
    int lab = __ldg(&ent_label[eg]);
    const float* tok = hidden + (size_t)(b * LL + idx) * HH;
    const float* emb = entity_emb + (size_t)lab * HH;
    size_t base = (size_t)eg * 2 * HH;
    for (int i = threadIdx.x; i < HH; i += blockDim.x) {
        bf16 h, l;
        split2(tok[i], h, l);
        g_repr_hi[base + i] = h;       g_repr_lo[base + i] = l;
        split2(emb[i], h, l);
        g_repr_hi[base + HH + i] = h;  g_repr_lo[base + HH + i] = l;
    }
}

// ---------------- kernel: weight transpose + split (5 jobs, z-indexed) -------
struct PrepJob { const float* src; bf16* dhi; bf16* dlo; int rows, cols, direct; };

__global__ void prep_weights(PrepJob j0, PrepJob j1, PrepJob j2, PrepJob j3, PrepJob j4) {
    PrepJob j = (blockIdx.z == 0) ? j0 : (blockIdx.z == 1) ? j1 :
                (blockIdx.z == 2) ? j2 : (blockIdx.z == 3) ? j3 : j4;
    __shared__ float tile[32][33];
    int tx = threadIdx.x, ty = threadIdx.y;        // 32 x 8
    int x = blockIdx.x * 32 + tx;
    if (j.direct) {
        for (int k = 0; k < 4; k++) {
            int r = blockIdx.y * 32 + ty + k * 8;
            if (r < j.rows && x < j.cols) {
                bf16 h, l; split2(j.src[(size_t)r * j.cols + x], h, l);
                j.dhi[(size_t)r * j.cols + x] = h;
                j.dlo[(size_t)r * j.cols + x] = l;
            }
        }
        return;
    }
    for (int k = 0; k < 4; k++) {
        int r = blockIdx.y * 32 + ty + k * 8;
        if (r < j.rows && x < j.cols) tile[ty + k * 8][tx] = j.src[(size_t)r * j.cols + x];
    }
    __syncthreads();
    int c = blockIdx.y * 32 + tx;                  // dst col = src row
    for (int k = 0; k < 4; k++) {
        int r = blockIdx.x * 32 + ty + k * 8;      // dst row = src col
        if (r < j.cols && c < j.rows) {
            bf16 h, l; split2(tile[tx][ty + k * 8], h, l);
            j.dhi[(size_t)r * j.rows + c] = h;
            j.dlo[(size_t)r * j.rows + c] = l;
        }
    }
}

// ---------------- tensor-core GEMM: C = (Ahi+Alo)(Bhi+Blo), 3x bf16 MMA ------
// A [M][K] row-major bf16 planes; B [N][K] row-major bf16 planes.
struct GArgs {
    const bf16 *Ahi, *Alo, *Bhi, *Blo;
    const float* bias;
    float* outF;
    bf16 *Chi, *Clo;
};

#define CPA16(saddr, gptr) \
    asm volatile("cp.async.cg.shared.global [%0], [%1], 16;\n" :: "r"(saddr), "l"(gptr))

#define MMA_BF16(c, a, b) asm volatile( \
    "mma.sync.aligned.m16n8k16.row.col.f32.bf16.bf16.f32 " \
    "{%0,%1,%2,%3}, {%4,%5,%6,%7}, {%8,%9}, {%0,%1,%2,%3};\n" \
    : "+f"(c[0]), "+f"(c[1]), "+f"(c[2]), "+f"(c[3]) \
    : "r"(a[0]), "r"(a[1]), "r"(a[2]), "r"(a[3]), "r"(b[0]), "r"(b[1]))

template<bool RELU>
__global__ __launch_bounds__(128)
void mma_gemm(GArgs arg0, GArgs arg1, int M, int N, int K) {
    GArgs ar = (blockIdx.z == 1) ? arg1 : arg0;
    // [stage][plane][row][40] ; plane stride 5120B, stage stride 10240B
    __shared__ __align__(16) bf16 As[2][2][64][40];
    __shared__ __align__(16) bf16 Bs[2][2][64][40];

    int tid  = threadIdx.x;
    int lane = tid & 31, warp = tid >> 5;
    int wm = warp >> 1, wn = warp & 1;
    int g  = lane >> 2, c2 = (lane & 3) * 2;
    int m0 = blockIdx.y * 64, n0 = blockIdx.x * 64;

    float C[2][4][4];
#pragma unroll
    for (int i = 0; i < 2; i++)
#pragma unroll
        for (int jn = 0; jn < 4; jn++)
#pragma unroll
            for (int kq = 0; kq < 4; kq++) C[i][jn][kq] = 0.0f;

    // cp.async staging: thread t loads row r = t>>1, half q = t&1 (16 bf16 = 2x16B)
    int r = tid >> 1, q = tid & 1;
    const bf16* gAhi = ar.Ahi + (size_t)(m0 + r) * K + q * 16;
    const bf16* gAlo = ar.Alo + (size_t)(m0 + r) * K + q * 16;
    const bf16* gBhi = ar.Bhi + (size_t)(n0 + r) * K + q * 16;
    const bf16* gBlo = ar.Blo + (size_t)(n0 + r) * K + q * 16;
    uint32_t aBase = (uint32_t)__cvta_generic_to_shared(&As[0][0][r][q * 16]);
    uint32_t bBase = (uint32_t)__cvta_generic_to_shared(&Bs[0][0][r][q * 16]);

    auto issue = [&](int s, int kt) {
        size_t go = (size_t)kt * 32;
        uint32_t a = aBase + s * 10240;
        uint32_t b = bBase + s * 10240;
        CPA16(a,             gAhi + go);
        CPA16(a + 16,        gAhi + go + 8);
        CPA16(a + 5120,      gAlo + go);
        CPA16(a + 5120 + 16, gAlo + go + 8);
        CPA16(b,             gBhi + go);
        CPA16(b + 16,        gBhi + go + 8);
        CPA16(b + 5120,      gBlo + go);
        CPA16(b + 5120 + 16, gBlo + go + 8);
        asm volatile("cp.async.commit_group;\n");
    };

    int KT = K >> 5;
    issue(0, 0);

    for (int kt = 0; kt < KT; kt++) {
        asm volatile("cp.async.wait_group 0;\n");
        __syncthreads();
        if (kt + 1 < KT) issue((kt + 1) & 1, kt + 1);
        int s = kt & 1;
#pragma unroll
        for (int kk = 0; kk < 32; kk += 16) {
            uint32_t aH[2][4], aL[2][4], bH[4][2], bL[4][2];
#pragma unroll
            for (int mt = 0; mt < 2; mt++) {
                int row = wm * 32 + mt * 16 + g;
                const bf16* ph = &As[s][0][row][kk + c2];
                const bf16* pl = &As[s][1][row][kk + c2];
                aH[mt][0] = *(const uint32_t*)(ph);
                aH[mt][1] = *(const uint32_t*)(ph + 8 * 40);
                aH[mt][2] = *(const uint32_t*)(ph + 8);
                aH[mt][3] = *(const uint32_t*)(ph + 8 * 40 + 8);
                aL[mt][0] = *(const uint32_t*)(pl);
                aL[mt][1] = *(const uint32_t*)(pl + 8 * 40);
                aL[mt][2] = *(const uint32_t*)(pl + 8);
                aL[mt][3] = *(const uint32_t*)(pl + 8 * 40 + 8);
            }
#pragma unroll
            for (int nt = 0; nt < 4; nt++) {
                int row = wn * 32 + nt * 8 + g;
                const bf16* ph = &Bs[s][0][row][kk + c2];
                const bf16* pl = &Bs[s][1][row][kk + c2];
                bH[nt][0] = *(const uint32_t*)(ph);
                bH[nt][1] = *(const uint32_t*)(ph + 8);
                bL[nt][0] = *(const uint32_t*)(pl);
                bL[nt][1] = *(const uint32_t*)(pl + 8);
            }
#pragma unroll
            for (int mt = 0; mt < 2; mt++)
#pragma unroll
                for (int nt = 0; nt < 4; nt++) {
                    MMA_BF16(C[mt][nt], aH[mt], bH[nt]);
                    MMA_BF16(C[mt][nt], aH[mt], bL[nt]);
                    MMA_BF16(C[mt][nt], aL[mt], bH[nt]);
                }
        }
        __syncthreads();
    }

    // epilogue
#pragma unroll
    for (int mt = 0; mt < 2; mt++) {
        int rowb = m0 + wm * 32 + mt * 16 + g;
#pragma unroll
        for (int half = 0; half < 2; half++) {
            int rr = rowb + half * 8;
#pragma unroll
            for (int nt = 0; nt < 4; nt++) {
                int col = n0 + wn * 32 + nt * 8 + c2;
                float v0 = C[mt][nt][half * 2 + 0];
                float v1 = C[mt][nt][half * 2 + 1];
                if (ar.bias) { v0 += __ldg(&ar.bias[col]); v1 += __ldg(&ar.bias[col + 1]); }
                if (RELU) { v0 = fmaxf(v0, 0.0f); v1 = fmaxf(v1, 0.0f); }
                size_t o = (size_t)rr * N + col;
                if (ar.outF) { float2 f2 = make_float2(v0, v1); *(float2*)(ar.outF + o) = f2; }
                if (ar.Chi) {
                    bf16 h0, l0, h1, l1;
                    split2(v0, h0, l0); split2(v1, h1, l1);
                    *(__nv_bfloat162*)(ar.Chi + o) = __halves2bfloat162(h0, h1);
                    *(__nv_bfloat162*)(ar.Clo + o) = __halves2bfloat162(l0, l1);
                }
            }
        }
    }
}

// ---------------- per-entity linear-term dots --------------------------------
__global__ void lin_kernel(const float* __restrict__ lin_W) {
    int gw   = (blockIdx.x * blockDim.x + threadIdx.x) >> 5;
    int lane = threadIdx.x & 31;
    if (gw >= BE) return;
    const float* h = g_heads + (size_t)gw * HD2;
    const float* t = g_tails + (size_t)gw * HD2;
    float a0 = 0, a1 = 0, a2 = 0, a3 = 0;
    for (int d = lane; d < HD2; d += 32) {
        float hw = h[d], tw = t[d];
        a0 += hw * lin_W[d * 2 + 0];
        a1 += hw * lin_W[d * 2 + 1];
        a2 += tw * lin_W[(HD2 + d) * 2 + 0];
        a3 += tw * lin_W[(HD2 + d) * 2 + 1];
    }
#pragma unroll
    for (int o = 16; o > 0; o >>= 1) {
        a0 += __shfl_down_sync(~0u, a0, o);
        a1 += __shfl_down_sync(~0u, a1, o);
        a2 += __shfl_down_sync(~0u, a2, o);
        a3 += __shfl_down_sync(~0u, a3, o);
    }
    if (lane == 0) {
        float* p = g_lin4 + (size_t)gw * 4;
        p[0] = a0; p[1] = a1; p[2] = a2; p[3] = a3;
    }
}

// ---------------- per-relation logits + CE partials ---------------------------
__global__ void rel_kernel(const int* __restrict__ rel_head,
                           const int* __restrict__ rel_tail,
                           const int* __restrict__ rel_label,
                           const float* __restrict__ lin_b,
                           float* __restrict__ logits_out) {
    __shared__ float wsum[8];
    int warp = threadIdx.x >> 5, lane = threadIdx.x & 31;
    int gr = blockIdx.x * 8 + warp;
    int b  = gr >> 15;
    int he = rel_head[gr], te = rel_tail[gr];
    const float4* hv = (const float4*)(g_heads + (size_t)(b * EE + he) * HD2);
    const float4* uv = (const float4*)(g_u + (size_t)(b * EE + te) * 2 * HD2);
    float a0 = 0.0f, a1 = 0.0f;
#pragma unroll
    for (int i = 0; i < 3; i++) {
        int idx = lane + i * 32;
        float4 h  = hv[idx];
        float4 u0 = uv[idx];
        float4 u1 = uv[idx + 96];
        a0 += h.x * u0.x + h.y * u0.y + h.z * u0.z + h.w * u0.w;
        a1 += h.x * u1.x + h.y * u1.y + h.z * u1.z + h.w * u1.w;
    }
#pragma unroll
    for (int o = 16; o > 0; o >>= 1) {
        a0 += __shfl_down_sync(~0u, a0, o);
        a1 += __shfl_down_sync(~0u, a1, o);
    }
    if (lane == 0) {
        const float* lh = g_lin4 + (size_t)(b * EE + he) * 4;
        const float* lt = g_lin4 + (size_t)(b * EE + te) * 4;
        float s0 = a0 + lh[0] + lt[2] + lin_b[0];
        float s1 = a1 + lh[1] + lt[3] + lin_b[1];
        logits_out[(size_t)gr * 2 + 0] = s0;
        logits_out[(size_t)gr * 2 + 1] = s1;
        int lab = rel_label[gr];
        float m   = fmaxf(s0, s1);
        float lse = m + logf(expf(s0 - m) + expf(s1 - m));
        wsum[warp] = lse - (lab ? s1 : s0);
    }
    __syncthreads();
    if (threadIdx.x == 0) {
        float s = 0.0f;
#pragma unroll
        for (int w = 0; w < 8; w++) s += wsum[w];
        g_partial[blockIdx.x] = s;
    }
}

__global__ void finalize(float* __restrict__ out, int write_loss) {
    __shared__ float s[256];
    float acc = 0.0f;
    for (int i = threadIdx.x; i < RELBLOCKS; i += 256) acc += g_partial[i];
    s[threadIdx.x] = acc;
    __syncthreads();
    for (int st = 128; st > 0; st >>= 1) {
        if (threadIdx.x < st) s[threadIdx.x] += s[threadIdx.x + st];
        __syncthreads();
    }
    if (threadIdx.x == 0 && write_loss) out[0] = s[0] / (float)RR;
}

// ---------------- launcher ----------------------------------------------------
#define SYM(p, s) do { if (!(p)) cudaGetSymbolAddress((void**)&(p), s); } while (0)

extern "C" void kernel_launch(void* const* d_in, const int* in_sizes, int n_in,
                              void* d_out, int out_size) {
    const float* hidden     = (const float*)d_in[0];
    const int*   ent_start  = (const int*)  d_in[1];
    const int*   ent_label  = (const int*)  d_in[2];
    const int*   rel_head   = (const int*)  d_in[3];
    const int*   rel_tail   = (const int*)  d_in[4];
    const int*   rel_label  = (const int*)  d_in[5];
    const float* entity_emb = (const float*)d_in[6];
    const float* head_W1 = (const float*)d_in[7];
    const float* head_b1 = (const float*)d_in[8];
    const float* head_W2 = (const float*)d_in[9];
    const float* head_b2 = (const float*)d_in[10];
    const float* tail_W1 = (const float*)d_in[11];
    const float* tail_b1 = (const float*)d_in[12];
    const float* tail_W2 = (const float*)d_in[13];
    const float* tail_b2 = (const float*)d_in[14];
    const float* bil_W   = (const float*)d_in[15];
    const float* lin_W   = (const float*)d_in[16];
    const float* lin_b   = (const float*)d_in[17];
    float* out = (float*)d_out;

    static bf16 *p_repr_hi = nullptr, *p_repr_lo, *p_w1h_hi, *p_w1h_lo,
                *p_w1t_hi, *p_w1t_lo, *p_w2h_hi, *p_w2h_lo, *p_w2t_hi, *p_w2t_lo,
                *p_bw_hi, *p_bw_lo, *p_hidh_hi, *p_hidh_lo, *p_hidt_hi, *p_hidt_lo,
                *p_tls_hi, *p_tls_lo;
    static float *p_heads = nullptr, *p_tails, *p_u;
    if (!p_repr_hi) {
        SYM(p_repr_hi, g_repr_hi); SYM(p_repr_lo, g_repr_lo);
        SYM(p_w1h_hi, g_w1h_hi);   SYM(p_w1h_lo, g_w1h_lo);
        SYM(p_w1t_hi, g_w1t_hi);   SYM(p_w1t_lo, g_w1t_lo);
        SYM(p_w2h_hi, g_w2h_hi);   SYM(p_w2h_lo, g_w2h_lo);
        SYM(p_w2t_hi, g_w2t_hi);   SYM(p_w2t_lo, g_w2t_lo);
        SYM(p_bw_hi, g_bw_hi);     SYM(p_bw_lo, g_bw_lo);
        SYM(p_hidh_hi, g_hidh_hi); SYM(p_hidh_lo, g_hidh_lo);
        SYM(p_hidt_hi, g_hidt_hi); SYM(p_hidt_lo, g_hidt_lo);
        SYM(p_tls_hi, g_tls_hi);   SYM(p_tls_lo, g_tls_lo);
        SYM(p_heads, g_heads);     SYM(p_tails, g_tails);
        SYM(p_u, g_u);
    }

    int loff = out_size - 2 * NREL;
    if (loff < 0) loff = 0;
    float* logits_out = out + loff;

    build_repr_split<<<BE, 256>>>(hidden, ent_start, ent_label, entity_emb);

    PrepJob j0 = { head_W1, p_w1h_hi, p_w1h_lo, 2 * HH, HH, 0 };
    PrepJob j1 = { tail_W1, p_w1t_hi, p_w1t_lo, 2 * HH, HH, 0 };
    PrepJob j2 = { head_W2, p_w2h_hi, p_w2h_lo, HH, HD2, 0 };
    PrepJob j3 = { tail_W2, p_w2t_hi, p_w2t_lo, HH, HD2, 0 };
    PrepJob j4 = { bil_W,   p_bw_hi,  p_bw_lo,  2 * HD2, HD2, 1 };
    prep_weights<<<dim3(24, 48, 5), dim3(32, 8)>>>(j0, j1, j2, j3, j4);

    // L1: [1024,1536] x [1536,768] -> hid (bf16 split), bias+ReLU
    {
        GArgs a0 = { p_repr_hi, p_repr_lo, p_w1h_hi, p_w1h_lo, head_b1,
                     nullptr, p_hidh_hi, p_hidh_lo };
        GArgs a1 = { p_repr_hi, p_repr_lo, p_w1t_hi, p_w1t_lo, tail_b1,
                     nullptr, p_hidt_hi, p_hidt_lo };
        mma_gemm<true><<<dim3(HH / 64, BE / 64, 2), 128>>>(a0, a1, BE, HH, 2 * HH);
    }
    // L2: [1024,768] x [768,384] -> heads (f32), tails (f32 + split), bias+ReLU
    {
        GArgs a0 = { p_hidh_hi, p_hidh_lo, p_w2h_hi, p_w2h_lo, head_b2,
                     p_heads, nullptr, nullptr };
        GArgs a1 = { p_hidt_hi, p_hidt_lo, p_w2t_hi, p_w2t_lo, tail_b2,
                     p_tails, p_tls_hi, p_tls_lo };
        mma_gemm<true><<<dim3(HD2 / 64, BE / 64, 2), 128>>>(a0, a1, BE, HD2, HH);
    }
    // U: [1024,384] x bilW[768,384]^T-view -> u (f32), no bias/relu
    {
        GArgs a0 = { p_tls_hi, p_tls_lo, p_bw_hi, p_bw_lo, nullptr,
                     p_u, nullptr, nullptr };
        mma_gemm<false><<<dim3(2 * HD2 / 64, BE / 64, 1), 128>>>(a0, a0, BE, 2 * HD2, HD2);
    }

    lin_kernel<<<BE * 32 / 256, 256>>>(lin_W);
    rel_kernel<<<RELBLOCKS, 256>>>(rel_head, rel_tail, rel_label, lin_b, logits_out);
    finalize<<<1, 256>>>(out, loff > 0 ? 1 : 0);
}